// round 1
// baseline (speedup 1.0000x reference)
#include <cuda_runtime.h>

// ReduceBoundingBoxes: decode + threshold + stable sort + greedy NMS.
// Single-block latency-oriented implementation.
//
// N = 9216 cells; expected ~920 valid (score > 0.9). Sorted boxes are kept in
// dynamic SMEM (worst case all 9216 fit: 9216*(16+4+1) B ~ 189 KB < 227 KB).
// Unsorted compacted arrays use __device__ global scratch (no allocations).

#define NCELL   9216
#define PDIM    96
#define WIDTHF  3072.0f
#define HEIGHTF 2304.0f
#define XPSF    32.0f   // WIDTH / 96, multiplies the ROW index (P dim)
#define YPSF    24.0f   // HEIGHT / 96, multiplies the COL index (Q dim)
#define NTHREADS 1024

// Unsorted compacted scratch (order nondeterministic; ranks make the final
// sorted arrays deterministic).
__device__ float  g_cscore[NCELL];
__device__ float4 g_cbox[NCELL];
__device__ int    g_corig[NCELL];

extern __shared__ unsigned char smem_raw[];

__global__ __launch_bounds__(NTHREADS, 1)
void rbb_nms_kernel(const float* __restrict__ x, float* __restrict__ out)
{
    // SMEM layout
    float4*        sbox   = (float4*)(smem_raw);                   // [9216] 16B
    float*         sscore = (float*)(smem_raw + NCELL * 16);       // [9216] 4B
    unsigned char* skeep  = (unsigned char*)(smem_raw + NCELL * 20); // [9216] 1B
    __shared__ int s_cnt;

    const int tid = threadIdx.x;

    if (tid == 0) s_cnt = 0;
    __syncthreads();

    // ---- Phase A: decode boxes, compact valid entries to global scratch ----
    #pragma unroll
    for (int c = tid; c < NCELL; c += NTHREADS) {
        float s = x[c];                       // prob = x[0][p][q]
        if (s > 0.9f) {
            int   p  = c / PDIM;
            int   q  = c - p * PDIM;
            float ii = (float)p * XPSF;
            float jj = (float)q * YPSF;
            float v1 = x[1 * NCELL + c];
            float v2 = x[2 * NCELL + c];
            float v3 = x[3 * NCELL + c];
            float v4 = x[4 * NCELL + c];
            float bx1 = v1 * WIDTHF  + ii;
            float by1 = v2 * HEIGHTF + jj;
            float bx2 = (v3 - v1) * WIDTHF  + ii;
            float by2 = (v4 - v2) * HEIGHTF + jj;
            int k = atomicAdd(&s_cnt, 1);
            g_cscore[k] = s;
            g_cbox[k]   = make_float4(bx1, by1, bx2, by2);
            g_corig[k]  = c;
        }
    }
    __syncthreads();
    const int M = s_cnt;

    // ---- Phase B: stable descending rank (score desc, orig-index asc) ----
    // Exactly reproduces jnp.argsort(-where(valid, s, -inf)) on the valid set.
    for (int k = tid; k < M; k += NTHREADS) {
        float sk = g_cscore[k];
        int   ok = g_corig[k];
        int   r  = 0;
        for (int j = 0; j < M; j++) {
            float sj = g_cscore[j];
            // distinct orig indices guarantee a unique rank (permutation)
            r += (sj > sk) || (sj == sk && g_corig[j] < ok);
        }
        sbox[r]   = g_cbox[k];
        sscore[r] = sk;
        skeep[r]  = 1;
    }
    __syncthreads();

    // ---- Phase C: greedy sequential NMS ----
    // One barrier per i. skeep[i] is a uniform read (no writes to j<=i this
    // iteration), and each surviving j is owned by exactly one thread, so
    // there are no intra-iteration races.
    for (int i = 0; i < M; i++) {
        __syncthreads();
        if (!skeep[i]) continue;              // uniform branch
        float4 bi = sbox[i];                  // LDS broadcast
        float  ai = (bi.z - bi.x) * (bi.w - bi.y);
        for (int j = i + 1 + tid; j < M; j += NTHREADS) {
            if (!skeep[j]) continue;
            float4 bj = sbox[j];
            float  aj = (bj.z - bj.x) * (bj.w - bj.y);
            float iw = fmaxf(fminf(bi.z, bj.z) - fmaxf(bi.x, bj.x), 0.0f);
            float ih = fmaxf(fminf(bi.w, bj.w) - fmaxf(bi.y, bj.y), 0.0f);
            float inter = iw * ih;
            float iou = inter / (ai + aj - inter + 1e-9f);
            if (iou > 0.5f) skeep[j] = 0;
        }
    }
    __syncthreads();

    // ---- Phase D: zero output, scatter kept rows ----
    float4* o4 = (float4*)out;                // 46080 floats = 11520 float4
    #pragma unroll
    for (int i = tid; i < (NCELL * 5) / 4; i += NTHREADS)
        o4[i] = make_float4(0.f, 0.f, 0.f, 0.f);
    __syncthreads();
    for (int r = tid; r < M; r += NTHREADS) {
        if (skeep[r]) {
            float4 b = sbox[r];
            out[r * 5 + 0] = sscore[r];
            out[r * 5 + 1] = b.x;
            out[r * 5 + 2] = b.y;
            out[r * 5 + 3] = b.z - b.x;
            out[r * 5 + 4] = b.w - b.y;
        }
    }
}

extern "C" void kernel_launch(void* const* d_in, const int* in_sizes, int n_in,
                              void* d_out, int out_size)
{
    (void)in_sizes; (void)n_in; (void)out_size;
    const float* x   = (const float*)d_in[0];
    float*       out = (float*)d_out;

    const size_t smem_bytes = (size_t)NCELL * 21;  // 16 + 4 + 1 bytes per entry
    cudaFuncSetAttribute(rbb_nms_kernel,
                         cudaFuncAttributeMaxDynamicSharedMemorySize,
                         (int)smem_bytes);

    rbb_nms_kernel<<<1, NTHREADS, smem_bytes>>>(x, out);
}

// round 2
// speedup vs baseline: 2.5439x; 2.5439x over previous
#include <cuda_runtime.h>

// ReduceBoundingBoxes: decode + threshold + stable sort + greedy NMS.
// Bitmask-matrix NMS pipeline:
//   memset g_cnt -> K1 decode/compact (+zero out) -> K2 stable rank/scatter
//   -> K3 parallel suppression bit-matrix -> K4 chunked sequential scan + output.

#define NCELL   9216
#define PDIM    96
#define WIDTHF  3072.0f
#define HEIGHTF 2304.0f
#define XPSF    32.0f    // multiplies ROW index (P dim)
#define YPSF    24.0f    // multiplies COL index (Q dim)
#define MAXNW   144      // ceil(9216/64)
#define SUP_SMEM_WORDS 22528   // 22528 * 8B = 180224 B of dynamic SMEM for K4

// -------- global scratch (static device memory; no runtime allocation) -----
__device__ int    g_cnt;
__device__ float  g_cscore[NCELL];
__device__ float4 g_cbox[NCELL];
__device__ int    g_corig[NCELL];
__device__ float  g_sscore[NCELL];
__device__ float4 g_sbox[NCELL];
__device__ unsigned long long g_sup[(size_t)NCELL * MAXNW];

// ---------------------------------------------------------------------------
// K1: decode boxes, compact valid (score > 0.9) entries, zero the output.
// grid = 36 x 256 (one thread per cell)
// ---------------------------------------------------------------------------
__global__ void k1_decode(const float* __restrict__ x, float* __restrict__ out)
{
    int tid = blockIdx.x * blockDim.x + threadIdx.x;   // 0..9215

    // zero output: 46080 floats = 11520 float4
    float4* o4 = (float4*)out;
    #pragma unroll
    for (int i = tid; i < (NCELL * 5) / 4; i += NCELL)
        o4[i] = make_float4(0.f, 0.f, 0.f, 0.f);

    int c = tid;
    float s = x[c];
    if (s > 0.9f) {
        int   p  = c / PDIM;
        int   q  = c - p * PDIM;
        float ii = (float)p * XPSF;
        float jj = (float)q * YPSF;
        float v1 = x[1 * NCELL + c];
        float v2 = x[2 * NCELL + c];
        float v3 = x[3 * NCELL + c];
        float v4 = x[4 * NCELL + c];
        float bx1 = v1 * WIDTHF  + ii;
        float by1 = v2 * HEIGHTF + jj;
        float bx2 = (v3 - v1) * WIDTHF  + ii;
        float by2 = (v4 - v2) * HEIGHTF + jj;
        int k = atomicAdd(&g_cnt, 1);
        g_cscore[k] = s;
        g_cbox[k]   = make_float4(bx1, by1, bx2, by2);
        g_corig[k]  = c;
    }
}

// ---------------------------------------------------------------------------
// K2: stable descending rank (score desc, original-index asc) over the M
// compacted entries; scatter into sorted arrays. grid = 36 x 256.
// Dynamic SMEM: M scores + M orig indices (worst case 72 KB).
// ---------------------------------------------------------------------------
extern __shared__ unsigned char k2_smem[];

__global__ void k2_rank()
{
    const int M = g_cnt;
    float* sc = (float*)k2_smem;            // [M]
    int*   so = (int*)(k2_smem + NCELL*4);  // [M]

    for (int i = threadIdx.x; i < M; i += blockDim.x) {
        sc[i] = g_cscore[i];
        so[i] = g_corig[i];
    }
    __syncthreads();

    int k = blockIdx.x * blockDim.x + threadIdx.x;
    if (k < M) {
        float sk = sc[k];
        int   ok = so[k];
        int   r  = 0;
        for (int j = 0; j < M; j++) {
            float sj = sc[j];
            r += (sj > sk) || (sj == sk && so[j] < ok);
        }
        g_sbox[r]   = g_cbox[k];
        g_sscore[r] = sk;
    }
}

// ---------------------------------------------------------------------------
// K3: suppression bit-matrix. Item (i, w): bits of boxes j in 64-word w with
// j > i and IoU(i,j) > 0.5. Only words w >= (i>>6) are ever read by K4.
// grid-stride over M * nw items.
// ---------------------------------------------------------------------------
__global__ void k3_supmat()
{
    const int M  = g_cnt;
    const int nw = (M + 63) >> 6;
    const int total = M * nw;
    const int stride = gridDim.x * blockDim.x;

    for (int it = blockIdx.x * blockDim.x + threadIdx.x; it < total; it += stride) {
        int i = it / nw;
        int w = it - i * nw;
        if (w < (i >> 6)) continue;          // never read by the scan

        float4 bi = g_sbox[i];
        float  ai = (bi.z - bi.x) * (bi.w - bi.y);

        int base = w << 6;
        int nb   = min(64, M - base);
        unsigned long long bits = 0;
        for (int b = 0; b < nb; b++) {
            int j = base + b;
            if (j > i) {
                float4 bj = g_sbox[j];
                float  aj = (bj.z - bj.x) * (bj.w - bj.y);
                float iw = fmaxf(fminf(bi.z, bj.z) - fmaxf(bi.x, bj.x), 0.0f);
                float ih = fmaxf(fminf(bi.w, bj.w) - fmaxf(bi.y, bj.y), 0.0f);
                float inter = iw * ih;
                float iou = inter / (ai + aj - inter + 1e-9f);
                if (iou > 0.5f) bits |= (1ull << b);
            }
        }
        g_sup[it] = bits;
    }
}

// ---------------------------------------------------------------------------
// K4: chunked sequential greedy reduction + output scatter. single block.
// Fast path: whole bit-matrix staged into SMEM (fits for M <= ~1340).
// ---------------------------------------------------------------------------
extern __shared__ unsigned long long k4_ssup[];

__global__ __launch_bounds__(1024, 1) void k4_scan(float* __restrict__ out)
{
    __shared__ unsigned long long skeep[MAXNW];

    const int M = g_cnt;
    if (M == 0) return;
    const int nw = (M + 63) >> 6;
    const bool fast = (M * nw) <= SUP_SMEM_WORDS;

    if (fast) {
        for (int i = threadIdx.x; i < M * nw; i += 1024)
            k4_ssup[i] = g_sup[i];
    }
    if (threadIdx.x < MAXNW) {
        int w = threadIdx.x;
        if (w < nw) {
            int nb = M - (w << 6);
            skeep[w] = (nb >= 64) ? ~0ull : ((1ull << nb) - 1ull);
        }
    }
    __syncthreads();

    if (threadIdx.x < 32) {
        const int lane = threadIdx.x;
        for (int c = 0; c < nw; c++) {
            const int base = c << 6;
            const int nb   = min(64, M - base);

            if (lane == 0) {
                // resolve intra-chunk greedy dependencies sequentially
                unsigned long long kw = skeep[c];
                for (int b = 0; b < nb; b++) {
                    if ((kw >> b) & 1ull) {
                        unsigned long long s = fast ? k4_ssup[(base + b) * nw + c]
                                                    : g_sup[(size_t)(base + b) * nw + c];
                        kw &= ~s;           // bits in s are all j > base+b
                    }
                }
                skeep[c] = kw;
            }
            __syncwarp();

            // apply surviving rows of this chunk to all future words, in parallel
            unsigned long long kw = skeep[c];
            for (int w = c + 1 + lane; w < nw; w += 32) {
                unsigned long long acc = 0;
                for (int b = 0; b < nb; b++)
                    if ((kw >> b) & 1ull)
                        acc |= fast ? k4_ssup[(base + b) * nw + w]
                                    : g_sup[(size_t)(base + b) * nw + w];
                skeep[w] &= ~acc;
            }
            __syncwarp();
        }
    }
    __syncthreads();

    // scatter kept rows (output already zeroed by K1)
    for (int r = threadIdx.x; r < M; r += 1024) {
        if ((skeep[r >> 6] >> (r & 63)) & 1ull) {
            float4 b = g_sbox[r];
            out[r * 5 + 0] = g_sscore[r];
            out[r * 5 + 1] = b.x;
            out[r * 5 + 2] = b.y;
            out[r * 5 + 3] = b.z - b.x;
            out[r * 5 + 4] = b.w - b.y;
        }
    }
}

// ---------------------------------------------------------------------------
extern "C" void kernel_launch(void* const* d_in, const int* in_sizes, int n_in,
                              void* d_out, int out_size)
{
    (void)in_sizes; (void)n_in; (void)out_size;
    const float* x   = (const float*)d_in[0];
    float*       out = (float*)d_out;

    void* cnt_addr = nullptr;
    cudaGetSymbolAddress(&cnt_addr, g_cnt);
    cudaMemsetAsync(cnt_addr, 0, sizeof(int));

    cudaFuncSetAttribute(k2_rank, cudaFuncAttributeMaxDynamicSharedMemorySize,
                         NCELL * 8);
    cudaFuncSetAttribute(k4_scan, cudaFuncAttributeMaxDynamicSharedMemorySize,
                         SUP_SMEM_WORDS * 8);

    k1_decode<<<NCELL / 256, 256>>>(x, out);
    k2_rank<<<NCELL / 256, 256, NCELL * 8>>>();
    k3_supmat<<<256, 256>>>();
    k4_scan<<<1, 1024, SUP_SMEM_WORDS * 8>>>(out);
}

// round 3
// speedup vs baseline: 2.9591x; 1.1632x over previous
#include <cuda_runtime.h>

// ReduceBoundingBoxes: decode + threshold + stable sort + greedy NMS.
// 3-launch pipeline:
//   KA (1 block)  : decode + compact + stable rank -> sorted arrays, g_cnt
//   KB (chip-wide): zero output + suppression bit-matrix (upper-tri words)
//   KC (1 block)  : chunked greedy reduction w/ pipelined loads + scatter

#define NCELL   9216
#define PDIM    96
#define WIDTHF  3072.0f
#define HEIGHTF 2304.0f
#define XPSF    32.0f    // multiplies ROW index (P dim)
#define YPSF    24.0f    // multiplies COL index (Q dim)
#define MAXNW   144      // ceil(9216/64)
#define SUP_SMEM_WORDS 22528   // 22528 * 8B = 180224 B dynamic SMEM in KC

// -------- global scratch (static device memory) ----------------------------
__device__ int    g_cnt;
__device__ float  g_sscore[NCELL];
__device__ float4 g_sbox[NCELL];
__device__ unsigned long long g_sup[(size_t)NCELL * MAXNW];

// ---------------------------------------------------------------------------
// KA: single block. Decode cells, compact valid (score > 0.9) via SMEM atomic,
// stable rank (score desc, orig asc), scatter sorted arrays to global.
// Dynamic SMEM: box 16B + score 4B + orig 4B per cell = 24B * 9216 = 221184 B.
// ---------------------------------------------------------------------------
extern __shared__ unsigned char ka_smem[];

__global__ __launch_bounds__(1024, 1) void ka_decode_rank(const float* __restrict__ x)
{
    float4* cbox   = (float4*)(ka_smem);                    // [9216]
    float*  cscore = (float*)(ka_smem + NCELL * 16);        // [9216]
    int*    corig  = (int*)(ka_smem + NCELL * 20);          // [9216]
    __shared__ int s_cnt;

    const int tid = threadIdx.x;
    if (tid == 0) s_cnt = 0;
    __syncthreads();

    #pragma unroll
    for (int c = tid; c < NCELL; c += 1024) {
        float s = x[c];
        if (s > 0.9f) {
            int   p  = c / PDIM;
            int   q  = c - p * PDIM;
            float ii = (float)p * XPSF;
            float jj = (float)q * YPSF;
            float v1 = x[1 * NCELL + c];
            float v2 = x[2 * NCELL + c];
            float v3 = x[3 * NCELL + c];
            float v4 = x[4 * NCELL + c];
            float bx1 = v1 * WIDTHF  + ii;
            float by1 = v2 * HEIGHTF + jj;
            float bx2 = (v3 - v1) * WIDTHF  + ii;
            float by2 = (v4 - v2) * HEIGHTF + jj;
            int k = atomicAdd(&s_cnt, 1);
            cbox[k]   = make_float4(bx1, by1, bx2, by2);
            cscore[k] = s;
            corig[k]  = c;
        }
    }
    __syncthreads();
    const int M = s_cnt;
    if (tid == 0) g_cnt = M;

    // stable descending rank: r = #{j: s_j > s_k or (s_j == s_k and o_j < o_k)}
    for (int k = tid; k < M; k += 1024) {
        float sk = cscore[k];
        int   ok = corig[k];
        int   r  = 0;
        for (int j = 0; j < M; j++) {
            float sj = cscore[j];
            r += (sj > sk) || (sj == sk && corig[j] < ok);
        }
        g_sbox[r]   = cbox[k];
        g_sscore[r] = sk;
    }
}

// ---------------------------------------------------------------------------
// KB: chip-wide. Zero the output, then build the suppression bit-matrix:
// word (i, w) = bits of boxes j in word w with j > i and IoU(i,j) > 0.5.
// Only words w >= (i>>6) are ever read by KC.
// ---------------------------------------------------------------------------
__global__ void kb_supmat(float* __restrict__ out)
{
    const int gtid   = blockIdx.x * blockDim.x + threadIdx.x;
    const int stride = gridDim.x * blockDim.x;

    // zero output: 46080 floats = 11520 float4
    for (int i = gtid; i < (NCELL * 5) / 4; i += stride)
        ((float4*)out)[i] = make_float4(0.f, 0.f, 0.f, 0.f);

    const int M  = g_cnt;
    const int nw = (M + 63) >> 6;
    const int total = M * nw;

    for (int it = gtid; it < total; it += stride) {
        int i = it / nw;
        int w = it - i * nw;
        if (w < (i >> 6)) continue;

        float4 bi = g_sbox[i];
        float  ai = (bi.z - bi.x) * (bi.w - bi.y);

        int base = w << 6;
        int nb   = min(64, M - base);
        unsigned long long bits = 0;
        for (int b = 0; b < nb; b++) {
            int j = base + b;
            if (j > i) {
                float4 bj = g_sbox[j];
                float  aj = (bj.z - bj.x) * (bj.w - bj.y);
                float iw = fmaxf(fminf(bi.z, bj.z) - fmaxf(bi.x, bj.x), 0.0f);
                float ih = fmaxf(fminf(bi.w, bj.w) - fmaxf(bi.y, bj.y), 0.0f);
                float inter = iw * ih;
                float iou = inter / (ai + aj - inter + 1e-9f);
                if (iou > 0.5f) bits |= (1ull << b);
            }
        }
        g_sup[it] = bits;
    }
}

// ---------------------------------------------------------------------------
// KC: single block. Chunked greedy reduction with PIPELINED (unconditional)
// loads, then scatter kept rows. Fast path stages the matrix in SMEM.
// ---------------------------------------------------------------------------
extern __shared__ unsigned long long kc_ssup[];

__global__ __launch_bounds__(1024, 1) void kc_scan(float* __restrict__ out)
{
    __shared__ unsigned long long skeep[MAXNW];

    const int M = g_cnt;
    if (M == 0) return;
    const int nw = (M + 63) >> 6;
    const int Mr = nw << 6;                         // rounded-up row count
    const bool fast = ((size_t)Mr * nw) <= SUP_SMEM_WORDS;

    if (fast) {
        const int used = M * nw;
        for (int i = threadIdx.x; i < used; i += 1024)
            kc_ssup[i] = g_sup[i];
        // zero the tail rows so unconditional tail loads are benign-but-defined
        for (int i = used + threadIdx.x; i < Mr * nw; i += 1024)
            kc_ssup[i] = 0ull;
    }
    if (threadIdx.x < nw) {
        int nb = M - (threadIdx.x << 6);
        skeep[threadIdx.x] = (nb >= 64) ? ~0ull : ((1ull << nb) - 1ull);
    }
    __syncthreads();

    if (threadIdx.x < 32) {
        const int lane = threadIdx.x;
        for (int c = 0; c < nw; c++) {
            const int base = c << 6;

            if (lane == 0) {
                // resolve intra-chunk dependencies; loads batched 8-wide so
                // they pipeline independent of the kw chain
                unsigned long long kw = skeep[c];
                #pragma unroll 1
                for (int b0 = 0; b0 < 64; b0 += 8) {
                    unsigned long long s0, s1, s2, s3, s4, s5, s6, s7;
                    if (fast) {
                        const unsigned long long* p = &kc_ssup[(size_t)(base + b0) * nw + c];
                        s0 = p[0*nw]; s1 = p[1*nw]; s2 = p[2*nw]; s3 = p[3*nw];
                        s4 = p[4*nw]; s5 = p[5*nw]; s6 = p[6*nw]; s7 = p[7*nw];
                    } else {
                        const unsigned long long* p = &g_sup[(size_t)(base + b0) * nw + c];
                        s0 = p[0*nw]; s1 = p[1*nw]; s2 = p[2*nw]; s3 = p[3*nw];
                        s4 = p[4*nw]; s5 = p[5*nw]; s6 = p[6*nw]; s7 = p[7*nw];
                    }
                    kw &= ~(((kw >> (b0+0)) & 1ull) ? s0 : 0ull);
                    kw &= ~(((kw >> (b0+1)) & 1ull) ? s1 : 0ull);
                    kw &= ~(((kw >> (b0+2)) & 1ull) ? s2 : 0ull);
                    kw &= ~(((kw >> (b0+3)) & 1ull) ? s3 : 0ull);
                    kw &= ~(((kw >> (b0+4)) & 1ull) ? s4 : 0ull);
                    kw &= ~(((kw >> (b0+5)) & 1ull) ? s5 : 0ull);
                    kw &= ~(((kw >> (b0+6)) & 1ull) ? s6 : 0ull);
                    kw &= ~(((kw >> (b0+7)) & 1ull) ? s7 : 0ull);
                }
                skeep[c] = kw;
            }
            __syncwarp();

            // apply this chunk's survivors to all future words in parallel;
            // unconditional loads + select keep the LDS stream pipelined
            const unsigned long long kw = skeep[c];
            if (kw) {
                for (int w = c + 1 + lane; w < nw; w += 32) {
                    unsigned long long acc = 0;
                    if (fast) {
                        const unsigned long long* p = &kc_ssup[(size_t)base * nw + w];
                        #pragma unroll
                        for (int b = 0; b < 64; b++)
                            acc |= ((kw >> b) & 1ull) ? p[(size_t)b * nw] : 0ull;
                    } else {
                        const unsigned long long* p = &g_sup[(size_t)base * nw + w];
                        #pragma unroll 8
                        for (int b = 0; b < 64; b++)
                            acc |= ((kw >> b) & 1ull) ? p[(size_t)b * nw] : 0ull;
                    }
                    skeep[w] &= ~acc;
                }
            }
            __syncwarp();
        }
    }
    __syncthreads();

    // scatter kept rows (output zeroed by KB)
    for (int r = threadIdx.x; r < M; r += 1024) {
        if ((skeep[r >> 6] >> (r & 63)) & 1ull) {
            float4 b = g_sbox[r];
            out[r * 5 + 0] = g_sscore[r];
            out[r * 5 + 1] = b.x;
            out[r * 5 + 2] = b.y;
            out[r * 5 + 3] = b.z - b.x;
            out[r * 5 + 4] = b.w - b.y;
        }
    }
}

// ---------------------------------------------------------------------------
extern "C" void kernel_launch(void* const* d_in, const int* in_sizes, int n_in,
                              void* d_out, int out_size)
{
    (void)in_sizes; (void)n_in; (void)out_size;
    const float* x   = (const float*)d_in[0];
    float*       out = (float*)d_out;

    cudaFuncSetAttribute(ka_decode_rank,
                         cudaFuncAttributeMaxDynamicSharedMemorySize,
                         NCELL * 24);
    cudaFuncSetAttribute(kc_scan,
                         cudaFuncAttributeMaxDynamicSharedMemorySize,
                         SUP_SMEM_WORDS * 8);

    ka_decode_rank<<<1, 1024, NCELL * 24>>>(x);
    kb_supmat<<<148, 256>>>(out);
    kc_scan<<<1, 1024, SUP_SMEM_WORDS * 8>>>(out);
}

// round 4
// speedup vs baseline: 3.3120x; 1.1193x over previous
#include <cuda_runtime.h>

// ReduceBoundingBoxes: decode + threshold + stable sort + greedy NMS.
// 4-launch pipeline, all parallel stages chip-wide:
//   KA1 (chip-wide): decode + compact valid entries (global atomic)
//   KA2 (chip-wide): stable rank per block from SMEM-staged scores -> sorted
//   KB  (chip-wide): zero output + suppression bit-matrix
//   KC  (1 block)  : chunked greedy reduction w/ pipelined loads + scatter

#define NCELL   9216
#define PDIM    96
#define WIDTHF  3072.0f
#define HEIGHTF 2304.0f
#define XPSF    32.0f    // multiplies ROW index (P dim)
#define YPSF    24.0f    // multiplies COL index (Q dim)
#define MAXNW   144      // ceil(9216/64)
#define SUP_SMEM_WORDS 22528   // 180224 B dynamic SMEM in KC

// -------- global scratch (static device memory) ----------------------------
__device__ int    g_cnt;
__device__ float  g_cscore[NCELL];
__device__ float4 g_cbox[NCELL];
__device__ int    g_corig[NCELL];
__device__ float  g_sscore[NCELL];
__device__ float4 g_sbox[NCELL];
__device__ unsigned long long g_sup[(size_t)NCELL * MAXNW];

// ---------------------------------------------------------------------------
// KA1: chip-wide decode + compaction. One thread per cell. Also resets g_cnt
// for the NEXT replay after publishing it? No - g_cnt must be zero on entry;
// thread 0 of a dedicated pre-pass can't work. Instead: cell 0's thread zeroes
// a *separate* counter? Simplest graph-safe scheme: zero g_cnt at the END of
// KC (single block, after everyone read it). First replay: g_cnt starts 0
// (static init). Subsequent replays: KC reset it. Deterministic.
// ---------------------------------------------------------------------------
__global__ void ka1_decode(const float* __restrict__ x)
{
    int c = blockIdx.x * blockDim.x + threadIdx.x;   // 0..9215
    float s = x[c];
    if (s > 0.9f) {
        int   p  = c / PDIM;
        int   q  = c - p * PDIM;
        float ii = (float)p * XPSF;
        float jj = (float)q * YPSF;
        float v1 = x[1 * NCELL + c];
        float v2 = x[2 * NCELL + c];
        float v3 = x[3 * NCELL + c];
        float v4 = x[4 * NCELL + c];
        float bx1 = v1 * WIDTHF  + ii;
        float by1 = v2 * HEIGHTF + jj;
        float bx2 = (v3 - v1) * WIDTHF  + ii;
        float by2 = (v4 - v2) * HEIGHTF + jj;
        int k = atomicAdd(&g_cnt, 1);
        g_cscore[k] = s;
        g_cbox[k]   = make_float4(bx1, by1, bx2, by2);
        g_corig[k]  = c;
    }
}

// ---------------------------------------------------------------------------
// KA2: chip-wide stable rank. Block b owns k in [b*256, b*256+256); blocks
// beyond M exit before staging. Each active block stages all M (score, orig)
// pairs into SMEM, then each thread counts its rank and scatters.
// Dynamic SMEM: NCELL * 8 B worst case = 72 KB.
// ---------------------------------------------------------------------------
extern __shared__ unsigned char ka2_smem[];

__global__ void ka2_rank()
{
    const int M = g_cnt;
    const int kbase = blockIdx.x * blockDim.x;
    if (kbase >= M) return;

    float* sc = (float*)ka2_smem;              // [M]
    int*   so = (int*)(ka2_smem + NCELL * 4);  // [M]

    for (int i = threadIdx.x; i < M; i += blockDim.x) {
        sc[i] = g_cscore[i];
        so[i] = g_corig[i];
    }
    __syncthreads();

    const int k = kbase + threadIdx.x;
    if (k < M) {
        float sk = sc[k];
        int   ok = so[k];
        int   r  = 0;
        for (int j = 0; j < M; j++) {
            float sj = sc[j];
            r += (sj > sk) || (sj == sk && so[j] < ok);
        }
        g_sbox[r]   = g_cbox[k];
        g_sscore[r] = sk;
    }
}

// ---------------------------------------------------------------------------
// KB: chip-wide. Zero the output, then build the suppression bit-matrix:
// word (i, w) = bits of boxes j in word w with j > i and IoU(i,j) > 0.5.
// Only words w >= (i>>6) are ever read by KC.
// ---------------------------------------------------------------------------
__global__ void kb_supmat(float* __restrict__ out)
{
    const int gtid   = blockIdx.x * blockDim.x + threadIdx.x;
    const int stride = gridDim.x * blockDim.x;

    for (int i = gtid; i < (NCELL * 5) / 4; i += stride)
        ((float4*)out)[i] = make_float4(0.f, 0.f, 0.f, 0.f);

    const int M  = g_cnt;
    const int nw = (M + 63) >> 6;
    const int total = M * nw;

    for (int it = gtid; it < total; it += stride) {
        int i = it / nw;
        int w = it - i * nw;
        if (w < (i >> 6)) continue;

        float4 bi = g_sbox[i];
        float  ai = (bi.z - bi.x) * (bi.w - bi.y);

        int base = w << 6;
        int nb   = min(64, M - base);
        unsigned long long bits = 0;
        for (int b = 0; b < nb; b++) {
            int j = base + b;
            if (j > i) {
                float4 bj = g_sbox[j];
                float  aj = (bj.z - bj.x) * (bj.w - bj.y);
                float iw = fmaxf(fminf(bi.z, bj.z) - fmaxf(bi.x, bj.x), 0.0f);
                float ih = fmaxf(fminf(bi.w, bj.w) - fmaxf(bi.y, bj.y), 0.0f);
                float inter = iw * ih;
                float iou = inter / (ai + aj - inter + 1e-9f);
                if (iou > 0.5f) bits |= (1ull << b);
            }
        }
        g_sup[it] = bits;
    }
}

// ---------------------------------------------------------------------------
// KC: single block. Chunked greedy reduction with pipelined loads + scatter.
// Also resets g_cnt at the very end (graph-replay contract; see KA1 comment).
// ---------------------------------------------------------------------------
extern __shared__ unsigned long long kc_ssup[];

__global__ __launch_bounds__(1024, 1) void kc_scan(float* __restrict__ out)
{
    __shared__ unsigned long long skeep[MAXNW];

    const int M = g_cnt;
    if (M == 0) { if (threadIdx.x == 0) g_cnt = 0; return; }
    const int nw = (M + 63) >> 6;
    const int Mr = nw << 6;
    const bool fast = ((size_t)Mr * nw) <= SUP_SMEM_WORDS;

    if (fast) {
        const int used = M * nw;
        for (int i = threadIdx.x; i < used; i += 1024)
            kc_ssup[i] = g_sup[i];
        for (int i = used + threadIdx.x; i < Mr * nw; i += 1024)
            kc_ssup[i] = 0ull;
    }
    if (threadIdx.x < nw) {
        int nb = M - (threadIdx.x << 6);
        skeep[threadIdx.x] = (nb >= 64) ? ~0ull : ((1ull << nb) - 1ull);
    }
    __syncthreads();

    if (threadIdx.x < 32) {
        const int lane = threadIdx.x;
        for (int c = 0; c < nw; c++) {
            const int base = c << 6;

            if (lane == 0) {
                unsigned long long kw = skeep[c];
                #pragma unroll 1
                for (int b0 = 0; b0 < 64; b0 += 8) {
                    unsigned long long s0, s1, s2, s3, s4, s5, s6, s7;
                    if (fast) {
                        const unsigned long long* p = &kc_ssup[(size_t)(base + b0) * nw + c];
                        s0 = p[0*nw]; s1 = p[1*nw]; s2 = p[2*nw]; s3 = p[3*nw];
                        s4 = p[4*nw]; s5 = p[5*nw]; s6 = p[6*nw]; s7 = p[7*nw];
                    } else {
                        const unsigned long long* p = &g_sup[(size_t)(base + b0) * nw + c];
                        s0 = p[0*nw]; s1 = p[1*nw]; s2 = p[2*nw]; s3 = p[3*nw];
                        s4 = p[4*nw]; s5 = p[5*nw]; s6 = p[6*nw]; s7 = p[7*nw];
                    }
                    kw &= ~(((kw >> (b0+0)) & 1ull) ? s0 : 0ull);
                    kw &= ~(((kw >> (b0+1)) & 1ull) ? s1 : 0ull);
                    kw &= ~(((kw >> (b0+2)) & 1ull) ? s2 : 0ull);
                    kw &= ~(((kw >> (b0+3)) & 1ull) ? s3 : 0ull);
                    kw &= ~(((kw >> (b0+4)) & 1ull) ? s4 : 0ull);
                    kw &= ~(((kw >> (b0+5)) & 1ull) ? s5 : 0ull);
                    kw &= ~(((kw >> (b0+6)) & 1ull) ? s6 : 0ull);
                    kw &= ~(((kw >> (b0+7)) & 1ull) ? s7 : 0ull);
                }
                skeep[c] = kw;
            }
            __syncwarp();

            const unsigned long long kw = skeep[c];
            if (kw) {
                for (int w = c + 1 + lane; w < nw; w += 32) {
                    unsigned long long acc = 0;
                    if (fast) {
                        const unsigned long long* p = &kc_ssup[(size_t)base * nw + w];
                        #pragma unroll
                        for (int b = 0; b < 64; b++)
                            acc |= ((kw >> b) & 1ull) ? p[(size_t)b * nw] : 0ull;
                    } else {
                        const unsigned long long* p = &g_sup[(size_t)base * nw + w];
                        #pragma unroll 8
                        for (int b = 0; b < 64; b++)
                            acc |= ((kw >> b) & 1ull) ? p[(size_t)b * nw] : 0ull;
                    }
                    skeep[w] &= ~acc;
                }
            }
            __syncwarp();
        }
    }
    __syncthreads();

    for (int r = threadIdx.x; r < M; r += 1024) {
        if ((skeep[r >> 6] >> (r & 63)) & 1ull) {
            float4 b = g_sbox[r];
            out[r * 5 + 0] = g_sscore[r];
            out[r * 5 + 1] = b.x;
            out[r * 5 + 2] = b.y;
            out[r * 5 + 3] = b.z - b.x;
            out[r * 5 + 4] = b.w - b.y;
        }
    }

    // reset the compaction counter for the next replay (deterministic:
    // every replay sees g_cnt == 0 on entry to KA1)
    __syncthreads();
    if (threadIdx.x == 0) g_cnt = 0;
}

// ---------------------------------------------------------------------------
extern "C" void kernel_launch(void* const* d_in, const int* in_sizes, int n_in,
                              void* d_out, int out_size)
{
    (void)in_sizes; (void)n_in; (void)out_size;
    const float* x   = (const float*)d_in[0];
    float*       out = (float*)d_out;

    cudaFuncSetAttribute(ka2_rank,
                         cudaFuncAttributeMaxDynamicSharedMemorySize,
                         NCELL * 8);
    cudaFuncSetAttribute(kc_scan,
                         cudaFuncAttributeMaxDynamicSharedMemorySize,
                         SUP_SMEM_WORDS * 8);

    ka1_decode<<<NCELL / 256, 256>>>(x);
    ka2_rank<<<NCELL / 256, 256, NCELL * 8>>>();
    kb_supmat<<<148, 256>>>(out);
    kc_scan<<<1, 1024, SUP_SMEM_WORDS * 8>>>(out);
}